// round 1
// baseline (speedup 1.0000x reference)
#include <cuda_runtime.h>

#define BB   2
#define SS   2048
#define HH   1024
#define NHH  16
#define DHH  64

// Scratch: Q/K/V in [B, NH, S, DH] layout. 16.8 MB each.
__device__ float g_q[BB*NHH*SS*DHH];
__device__ float g_k[BB*NHH*SS*DHH];
__device__ float g_v[BB*NHH*SS*DHH];

// ---------------------------------------------------------------------------
// QKV projection GEMM: out[b,h,s,d] = sum_k hid[b,s,k] * W[h*DH+d, k] + bias[n]
// 64x64 output tile per CTA, 256 threads, 4x4 microtile per thread.
// blockIdx.z selects which of Q/K/V.
// ---------------------------------------------------------------------------
__global__ __launch_bounds__(256) void qkv_kernel(
    const float* __restrict__ hid,
    const float* __restrict__ Wq, const float* __restrict__ bq,
    const float* __restrict__ Wk, const float* __restrict__ bk,
    const float* __restrict__ Wv, const float* __restrict__ bv)
{
    const float* Wsrc;
    const float* bsrc;
    float* outp;
    if (blockIdx.z == 0)      { Wsrc = Wq; bsrc = bq; outp = g_q; }
    else if (blockIdx.z == 1) { Wsrc = Wk; bsrc = bk; outp = g_k; }
    else                      { Wsrc = Wv; bsrc = bv; outp = g_v; }

    __shared__ float As[16][68];   // [k][m]
    __shared__ float Bs[16][68];   // [k][n]

    const int tid = threadIdx.x;
    const int tx  = tid & 15;
    const int ty  = tid >> 4;
    const int m0  = blockIdx.y * 64;
    const int n0  = blockIdx.x * 64;

    const int lrow = tid >> 2;        // 0..63
    const int lk   = (tid & 3) * 4;   // 0,4,8,12

    const float* Aptr = hid  + (size_t)(m0 + lrow) * HH + lk;
    const float* Wptr = Wsrc + (size_t)(n0 + lrow) * HH + lk;

    float c[4][4] = {};

    for (int k0 = 0; k0 < HH; k0 += 16) {
        float4 a = *(const float4*)(Aptr + k0);
        float4 w = *(const float4*)(Wptr + k0);
        __syncthreads();
        As[lk+0][lrow] = a.x; As[lk+1][lrow] = a.y;
        As[lk+2][lrow] = a.z; As[lk+3][lrow] = a.w;
        Bs[lk+0][lrow] = w.x; Bs[lk+1][lrow] = w.y;
        Bs[lk+2][lrow] = w.z; Bs[lk+3][lrow] = w.w;
        __syncthreads();
        #pragma unroll
        for (int kk = 0; kk < 16; kk++) {
            float4 av = *(const float4*)&As[kk][ty*4];
            float4 wv = *(const float4*)&Bs[kk][tx*4];
            float am[4] = {av.x, av.y, av.z, av.w};
            float wm[4] = {wv.x, wv.y, wv.z, wv.w};
            #pragma unroll
            for (int i = 0; i < 4; i++)
                #pragma unroll
                for (int j = 0; j < 4; j++)
                    c[i][j] += am[i] * wm[j];
        }
    }

    // Epilogue: write in [B, NH, S, DH] layout. n-tile width == DH, so one head.
    const int head = n0 >> 6;
    float b0 = bsrc[n0 + tx*4 + 0];
    float b1 = bsrc[n0 + tx*4 + 1];
    float b2 = bsrc[n0 + tx*4 + 2];
    float b3 = bsrc[n0 + tx*4 + 3];
    #pragma unroll
    for (int i = 0; i < 4; i++) {
        int m    = m0 + ty*4 + i;
        int bat  = m >> 11;          // m / S
        int srow = m & (SS - 1);
        float4 o;
        o.x = c[i][0] + b0; o.y = c[i][1] + b1;
        o.z = c[i][2] + b2; o.w = c[i][3] + b3;
        *(float4*)&outp[(((size_t)bat*NHH + head)*SS + srow)*DHH + tx*4] = o;
    }
}

// ---------------------------------------------------------------------------
// Flash-attention style: one CTA per (b, h, 64-row q tile). 256 threads.
// Online softmax with 16-lane shuffle row reductions.
// ---------------------------------------------------------------------------
#define ATTN_SMEM_FLOATS (64*68*3 + 64*64)

__global__ __launch_bounds__(256) void attn_kernel(
    const float* __restrict__ bias, float* __restrict__ out)
{
    extern __shared__ float sm[];
    float* Qs = sm;               // [d][row]  64x68
    float* Ks = Qs + 64*68;       // [d][kv]   64x68
    float* Ps = Ks + 64*68;       // [kv][row] 64x68
    float* Vs = Ps + 64*68;       // [kv][d]   64x64

    const int tid = threadIdx.x;
    const int tx  = tid & 15;
    const int ty  = tid >> 4;
    const int q0  = blockIdx.x * 64;
    const int h   = blockIdx.y;
    const int b   = blockIdx.z;

    const float* Qg = g_q + (((size_t)b*NHH + h)*SS + q0)*DHH;
    const float* Kg = g_k + (((size_t)b*NHH + h)*SS)*DHH;
    const float* Vg = g_v + (((size_t)b*NHH + h)*SS)*DHH;
    const float* Bg = bias + ((size_t)h*SS + q0)*SS;

    // Load Q tile, transposed into Qs[d][row]
    #pragma unroll
    for (int it = 0; it < 4; it++) {
        int idx = tid + it*256;
        int row = idx >> 4;
        int col = (idx & 15) * 4;
        float4 v = *(const float4*)(Qg + row*DHH + col);
        Qs[(col+0)*68 + row] = v.x; Qs[(col+1)*68 + row] = v.y;
        Qs[(col+2)*68 + row] = v.z; Qs[(col+3)*68 + row] = v.w;
    }

    float acc[4][4] = {};
    float mrow[4], lsum[4];
    #pragma unroll
    for (int i = 0; i < 4; i++) { mrow[i] = -1e30f; lsum[i] = 0.0f; }

    for (int kt = 0; kt < SS/64; kt++) {
        const int kv0 = kt * 64;

        __syncthreads();   // previous iteration's readers of Ks/Vs done
        #pragma unroll
        for (int it = 0; it < 4; it++) {
            int idx = tid + it*256;
            int row = idx >> 4;
            int col = (idx & 15) * 4;
            float4 kvv = *(const float4*)(Kg + (size_t)(kv0+row)*DHH + col);
            Ks[(col+0)*68 + row] = kvv.x; Ks[(col+1)*68 + row] = kvv.y;
            Ks[(col+2)*68 + row] = kvv.z; Ks[(col+3)*68 + row] = kvv.w;
            float4 vvv = *(const float4*)(Vg + (size_t)(kv0+row)*DHH + col);
            *(float4*)&Vs[row*64 + col] = vvv;
        }
        __syncthreads();

        // S = Q K^T (64-deep dot products)
        float s[4][4] = {};
        #pragma unroll 8
        for (int d = 0; d < 64; d++) {
            float4 qv = *(const float4*)&Qs[d*68 + ty*4];
            float4 kv = *(const float4*)&Ks[d*68 + tx*4];
            float qm[4] = {qv.x, qv.y, qv.z, qv.w};
            float km[4] = {kv.x, kv.y, kv.z, kv.w};
            #pragma unroll
            for (int i = 0; i < 4; i++)
                #pragma unroll
                for (int j = 0; j < 4; j++)
                    s[i][j] += qm[i] * km[j];
        }

        // scale + ALiBi bias
        #pragma unroll
        for (int i = 0; i < 4; i++) {
            float4 bv = *(const float4*)(Bg + (size_t)(ty*4 + i)*SS + kv0 + tx*4);
            s[i][0] = s[i][0]*0.125f + bv.x;
            s[i][1] = s[i][1]*0.125f + bv.y;
            s[i][2] = s[i][2]*0.125f + bv.z;
            s[i][3] = s[i][3]*0.125f + bv.w;
        }

        // online softmax (row groups are 16 consecutive lanes)
        #pragma unroll
        for (int i = 0; i < 4; i++) {
            float mx = fmaxf(fmaxf(s[i][0], s[i][1]), fmaxf(s[i][2], s[i][3]));
            #pragma unroll
            for (int o = 1; o < 16; o <<= 1)
                mx = fmaxf(mx, __shfl_xor_sync(0xFFFFFFFFu, mx, o));
            float mnew  = fmaxf(mrow[i], mx);
            float scale = __expf(mrow[i] - mnew);
            mrow[i] = mnew;
            float rs = 0.0f;
            #pragma unroll
            for (int j = 0; j < 4; j++) {
                s[i][j] = __expf(s[i][j] - mnew);
                rs += s[i][j];
            }
            #pragma unroll
            for (int o = 1; o < 16; o <<= 1)
                rs += __shfl_xor_sync(0xFFFFFFFFu, rs, o);
            lsum[i] = lsum[i]*scale + rs;
            #pragma unroll
            for (int j = 0; j < 4; j++) acc[i][j] *= scale;
        }

        // write P transposed: Ps[kv][row]
        #pragma unroll
        for (int i = 0; i < 4; i++)
            #pragma unroll
            for (int j = 0; j < 4; j++)
                Ps[(tx*4 + j)*68 + ty*4 + i] = s[i][j];
        __syncthreads();

        // acc += P V
        #pragma unroll 8
        for (int kv = 0; kv < 64; kv++) {
            float4 pv = *(const float4*)&Ps[kv*68 + ty*4];
            float4 vv = *(const float4*)&Vs[kv*64 + tx*4];
            float pm[4] = {pv.x, pv.y, pv.z, pv.w};
            float vm[4] = {vv.x, vv.y, vv.z, vv.w};
            #pragma unroll
            for (int i = 0; i < 4; i++)
                #pragma unroll
                for (int j = 0; j < 4; j++)
                    acc[i][j] += pm[i] * vm[j];
        }
    }

    // epilogue: out[b, s, h*DH + d]
    #pragma unroll
    for (int i = 0; i < 4; i++) {
        float inv = 1.0f / lsum[i];
        int srow = q0 + ty*4 + i;
        float4 o;
        o.x = acc[i][0]*inv; o.y = acc[i][1]*inv;
        o.z = acc[i][2]*inv; o.w = acc[i][3]*inv;
        *(float4*)&out[((size_t)b*SS + srow)*HH + h*DHH + tx*4] = o;
    }
}

extern "C" void kernel_launch(void* const* d_in, const int* in_sizes, int n_in,
                              void* d_out, int out_size)
{
    const float* hid  = (const float*)d_in[0];
    const float* bias = (const float*)d_in[1];
    const float* Wq   = (const float*)d_in[2];
    const float* bq   = (const float*)d_in[3];
    const float* Wk   = (const float*)d_in[4];
    const float* bk   = (const float*)d_in[5];
    const float* Wv   = (const float*)d_in[6];
    const float* bv   = (const float*)d_in[7];
    float* out = (float*)d_out;

    (void)in_sizes; (void)n_in; (void)out_size;

    cudaFuncSetAttribute(attn_kernel, cudaFuncAttributeMaxDynamicSharedMemorySize,
                         ATTN_SMEM_FLOATS * (int)sizeof(float));

    dim3 g1(HH/64, (BB*SS)/64, 3);
    qkv_kernel<<<g1, 256>>>(hid, Wq, bq, Wk, bk, Wv, bv);

    dim3 g2(SS/64, NHH, BB);
    attn_kernel<<<g2, 256, ATTN_SMEM_FLOATS * (int)sizeof(float)>>>(bias, out);
}

// round 2
// speedup vs baseline: 2.5528x; 2.5528x over previous
#include <cuda_runtime.h>

#define BB   2
#define SS   2048
#define HH   1024
#define NHH  16
#define DHH  64

// Scratch: Q/K/V in [B, NH, S, DH] layout (fp32).
__device__ float g_q[BB*NHH*SS*DHH];
__device__ float g_k[BB*NHH*SS*DHH];
__device__ float g_v[BB*NHH*SS*DHH];

__device__ __forceinline__ unsigned f2tf32(float x) {
    unsigned t;
    asm("cvt.rna.tf32.f32 %0, %1;" : "=r"(t) : "f"(x));
    return t;
}

__device__ __forceinline__ void mma_tf32(float* c,
    unsigned a0, unsigned a1, unsigned a2, unsigned a3,
    unsigned b0, unsigned b1)
{
    asm volatile(
        "mma.sync.aligned.m16n8k8.row.col.f32.tf32.tf32.f32 "
        "{%0,%1,%2,%3}, {%4,%5,%6,%7}, {%8,%9}, {%0,%1,%2,%3};"
        : "+f"(c[0]), "+f"(c[1]), "+f"(c[2]), "+f"(c[3])
        : "r"(a0), "r"(a1), "r"(a2), "r"(a3), "r"(b0), "r"(b1));
}

// Fast exp on the FMA pipe: exp(x) = 2^(x*log2e), rint via float-magic,
// deg-5 poly on f in [-0.5,0.5]. Rel err ~2.4e-6.
__device__ __forceinline__ float fexp(float x) {
    x = fmaxf(x, -87.0f);
    float y = x * 1.4426950408889634f;
    float r = y + 12582912.0f;            // rint(y) captured in mantissa
    float n = r - 12582912.0f;
    float f = y - n;                      // [-0.5, 0.5]
    float p = 1.3333558146e-3f;
    p = fmaf(p, f, 9.6181291076e-3f);
    p = fmaf(p, f, 5.5504108664e-2f);
    p = fmaf(p, f, 2.4022650696e-1f);
    p = fmaf(p, f, 6.9314718056e-1f);
    p = fmaf(p, f, 1.0f);
    int sc = (__float_as_int(r) - 0x4B400000 + 127) << 23;  // 2^n
    return p * __int_as_float(sc);
}

// ---------------------------------------------------------------------------
// QKV projection: out[b,h,s,d] = sum_k hid[m,k]*W[n,k] + bias[n]
// CTA: 128(M) x 64(N), ktile 32, 8 warps each 16x64. tf32 mma.
// ---------------------------------------------------------------------------
__global__ __launch_bounds__(256) void qkv_kernel(
    const float* __restrict__ hid,
    const float* __restrict__ Wq, const float* __restrict__ bq,
    const float* __restrict__ Wk, const float* __restrict__ bk,
    const float* __restrict__ Wv, const float* __restrict__ bv)
{
    const float* Wsrc; const float* bsrc; float* outp;
    if (blockIdx.z == 0)      { Wsrc = Wq; bsrc = bq; outp = g_q; }
    else if (blockIdx.z == 1) { Wsrc = Wk; bsrc = bk; outp = g_k; }
    else                      { Wsrc = Wv; bsrc = bv; outp = g_v; }

    __shared__ unsigned As[128*36];   // [m][k], stride 36 (==4 mod 32)
    __shared__ unsigned Ws[64*36];    // [n][k]

    const int tid  = threadIdx.x;
    const int warp = tid >> 5;
    const int lane = tid & 31;
    const int gid  = lane >> 2;    // 0..7
    const int tg   = lane & 3;     // 0..3
    const int m0   = blockIdx.y * 128;
    const int n0   = blockIdx.x * 64;
    const int mw   = warp * 16;

    float acc[8][4];
    #pragma unroll
    for (int i = 0; i < 8; i++)
        #pragma unroll
        for (int j = 0; j < 4; j++) acc[i][j] = 0.0f;

    for (int k0 = 0; k0 < HH; k0 += 32) {
        __syncthreads();
        #pragma unroll
        for (int it = 0; it < 4; it++) {
            int linear = tid + it*256;           // 0..1023
            int row = linear >> 3;
            int col = (linear & 7) * 4;
            float4 v = *(const float4*)(hid + (size_t)(m0+row)*HH + k0 + col);
            As[row*36+col+0] = f2tf32(v.x); As[row*36+col+1] = f2tf32(v.y);
            As[row*36+col+2] = f2tf32(v.z); As[row*36+col+3] = f2tf32(v.w);
        }
        #pragma unroll
        for (int it = 0; it < 2; it++) {
            int linear = tid + it*256;           // 0..511
            int row = linear >> 3;
            int col = (linear & 7) * 4;
            float4 v = *(const float4*)(Wsrc + (size_t)(n0+row)*HH + k0 + col);
            Ws[row*36+col+0] = f2tf32(v.x); Ws[row*36+col+1] = f2tf32(v.y);
            Ws[row*36+col+2] = f2tf32(v.z); Ws[row*36+col+3] = f2tf32(v.w);
        }
        __syncthreads();

        #pragma unroll
        for (int ks = 0; ks < 4; ks++) {
            int kb = ks * 8;
            unsigned a0 = As[(mw+gid  )*36 + kb + tg];
            unsigned a1 = As[(mw+gid+8)*36 + kb + tg];
            unsigned a2 = As[(mw+gid  )*36 + kb + tg + 4];
            unsigned a3 = As[(mw+gid+8)*36 + kb + tg + 4];
            #pragma unroll
            for (int nt = 0; nt < 8; nt++) {
                unsigned b0 = Ws[(nt*8+gid)*36 + kb + tg];
                unsigned b1 = Ws[(nt*8+gid)*36 + kb + tg + 4];
                mma_tf32(acc[nt], a0, a1, a2, a3, b0, b1);
            }
        }
    }

    const int head = blockIdx.x;   // n-tile width == DH
    const float qscale = (blockIdx.z == 0) ? 0.125f : 1.0f;
    int m    = m0 + mw + gid;
    int bat0 = m >> 11,        srow0 = m & (SS-1);
    int bat1 = (m+8) >> 11,    srow1 = (m+8) & (SS-1);
    #pragma unroll
    for (int nt = 0; nt < 8; nt++) {
        int d = nt*8 + tg*2;
        float b0 = bsrc[n0 + d], b1 = bsrc[n0 + d + 1];
        float2 o0, o1;
        o0.x = (acc[nt][0]+b0)*qscale; o0.y = (acc[nt][1]+b1)*qscale;
        o1.x = (acc[nt][2]+b0)*qscale; o1.y = (acc[nt][3]+b1)*qscale;
        *(float2*)&outp[(((size_t)bat0*NHH+head)*SS+srow0)*DHH + d] = o0;
        *(float2*)&outp[(((size_t)bat1*NHH+head)*SS+srow1)*DHH + d] = o1;
    }
}

// ---------------------------------------------------------------------------
// Attention: CTA = (b, h, 128 q-rows). 8 warps, warp = 16 rows x 64 cols.
// tf32 mma for QK^T and PV; unnormalized exp (no max pass); one epilogue div.
// Smem strides: 68 (==4 mod 32) for row-indexed-by-gid patterns,
//               72 (==8 mod 32) for V's k-indexed-by-tg pattern.
// ---------------------------------------------------------------------------
#define SM_K   (64*68)
#define SM_V   (64*72)
#define SM_PQ  (128*68)
#define ATTN_SMEM_U32 (SM_PQ + SM_K + SM_V)

__global__ __launch_bounds__(256) void attn_kernel(
    const float* __restrict__ bias, float* __restrict__ out)
{
    extern __shared__ unsigned sm[];
    unsigned* PQs = sm;                 // Q tile, reused as P tile after preload
    unsigned* Ks  = PQs + SM_PQ;
    unsigned* Vs  = Ks + SM_K;

    const int tid  = threadIdx.x;
    const int warp = tid >> 5;
    const int lane = tid & 31;
    const int gid  = lane >> 2;
    const int tg   = lane & 3;
    const int q0   = blockIdx.x * 128;
    const int h    = blockIdx.y;
    const int b    = blockIdx.z;
    const int mw   = warp * 16;

    const float* Qg = g_q + (((size_t)b*NHH + h)*SS + q0)*DHH;
    const float* Kg = g_k + (((size_t)b*NHH + h)*SS)*DHH;
    const float* Vg = g_v + (((size_t)b*NHH + h)*SS)*DHH;
    const float* Bg = bias + ((size_t)h*SS + q0)*SS;

    // Load Q tile (128x64) into smem as tf32
    #pragma unroll
    for (int it = 0; it < 8; it++) {
        int linear = tid + it*256;
        int row = linear >> 4;
        int col = (linear & 15) * 4;
        float4 v = *(const float4*)(Qg + (size_t)row*DHH + col);
        PQs[row*68+col+0] = f2tf32(v.x); PQs[row*68+col+1] = f2tf32(v.y);
        PQs[row*68+col+2] = f2tf32(v.z); PQs[row*68+col+3] = f2tf32(v.w);
    }
    __syncthreads();

    // Preload Q fragments (held in registers for the whole kernel)
    unsigned qa[8][4];
    #pragma unroll
    for (int ks = 0; ks < 8; ks++) {
        int kb = ks*8;
        qa[ks][0] = PQs[(mw+gid  )*68 + kb + tg];
        qa[ks][1] = PQs[(mw+gid+8)*68 + kb + tg];
        qa[ks][2] = PQs[(mw+gid  )*68 + kb + tg + 4];
        qa[ks][3] = PQs[(mw+gid+8)*68 + kb + tg + 4];
    }

    float acc[8][4];
    #pragma unroll
    for (int i = 0; i < 8; i++)
        #pragma unroll
        for (int j = 0; j < 4; j++) acc[i][j] = 0.0f;
    float lsum0 = 0.0f, lsum1 = 0.0f;

    const float* Brow0 = Bg + (size_t)(mw+gid)*SS;
    const float* Brow1 = Brow0 + 8*SS;

    for (int kt = 0; kt < SS/64; kt++) {
        const int kv0 = kt * 64;

        __syncthreads();    // prev iter's PV readers done -> safe to overwrite K/V
        #pragma unroll
        for (int it = 0; it < 4; it++) {
            int linear = tid + it*256;
            int row = linear >> 4;
            int col = (linear & 15) * 4;
            float4 kv = *(const float4*)(Kg + (size_t)(kv0+row)*DHH + col);
            Ks[row*68+col+0] = f2tf32(kv.x); Ks[row*68+col+1] = f2tf32(kv.y);
            Ks[row*68+col+2] = f2tf32(kv.z); Ks[row*68+col+3] = f2tf32(kv.w);
            float4 vv = *(const float4*)(Vg + (size_t)(kv0+row)*DHH + col);
            Vs[row*72+col+0] = f2tf32(vv.x); Vs[row*72+col+1] = f2tf32(vv.y);
            Vs[row*72+col+2] = f2tf32(vv.z); Vs[row*72+col+3] = f2tf32(vv.w);
        }
        __syncthreads();

        // S = Q K^T in two n-halves (limits live registers), then exp -> P smem
        #pragma unroll
        for (int half = 0; half < 2; half++) {
            float s[4][4];
            #pragma unroll
            for (int i = 0; i < 4; i++)
                #pragma unroll
                for (int j = 0; j < 4; j++) s[i][j] = 0.0f;
            #pragma unroll
            for (int ks = 0; ks < 8; ks++) {
                int kb = ks*8;
                #pragma unroll
                for (int n4 = 0; n4 < 4; n4++) {
                    int nt = half*4 + n4;
                    unsigned b0 = Ks[(nt*8+gid)*68 + kb + tg];
                    unsigned b1 = Ks[(nt*8+gid)*68 + kb + tg + 4];
                    mma_tf32(s[n4], qa[ks][0], qa[ks][1], qa[ks][2], qa[ks][3], b0, b1);
                }
            }
            #pragma unroll
            for (int n4 = 0; n4 < 4; n4++) {
                int nt = half*4 + n4;
                int c  = nt*8 + tg*2;
                float2 bv0 = *(const float2*)(Brow0 + kv0 + c);
                float2 bv1 = *(const float2*)(Brow1 + kv0 + c);
                float p0 = fexp(s[n4][0] + bv0.x);
                float p1 = fexp(s[n4][1] + bv0.y);
                float p2 = fexp(s[n4][2] + bv1.x);
                float p3 = fexp(s[n4][3] + bv1.y);
                lsum0 += p0 + p1;
                lsum1 += p2 + p3;
                PQs[(mw+gid  )*68 + c    ] = f2tf32(p0);
                PQs[(mw+gid  )*68 + c + 1] = f2tf32(p1);
                PQs[(mw+gid+8)*68 + c    ] = f2tf32(p2);
                PQs[(mw+gid+8)*68 + c + 1] = f2tf32(p3);
            }
        }
        __syncthreads();

        // acc += P V
        #pragma unroll
        for (int ks = 0; ks < 8; ks++) {
            int kb = ks*8;
            unsigned a0 = PQs[(mw+gid  )*68 + kb + tg];
            unsigned a1 = PQs[(mw+gid+8)*68 + kb + tg];
            unsigned a2 = PQs[(mw+gid  )*68 + kb + tg + 4];
            unsigned a3 = PQs[(mw+gid+8)*68 + kb + tg + 4];
            #pragma unroll
            for (int nt = 0; nt < 8; nt++) {
                unsigned b0 = Vs[(kb+tg  )*72 + nt*8 + gid];
                unsigned b1 = Vs[(kb+tg+4)*72 + nt*8 + gid];
                mma_tf32(acc[nt], a0, a1, a2, a3, b0, b1);
            }
        }
    }

    // Row sums complete across the quad
    lsum0 += __shfl_xor_sync(0xFFFFFFFFu, lsum0, 1);
    lsum0 += __shfl_xor_sync(0xFFFFFFFFu, lsum0, 2);
    lsum1 += __shfl_xor_sync(0xFFFFFFFFu, lsum1, 1);
    lsum1 += __shfl_xor_sync(0xFFFFFFFFu, lsum1, 2);
    float inv0 = 1.0f / lsum0;
    float inv1 = 1.0f / lsum1;

    int srow = q0 + mw + gid;
    #pragma unroll
    for (int nt = 0; nt < 8; nt++) {
        int d = nt*8 + tg*2;
        float2 o0, o1;
        o0.x = acc[nt][0]*inv0; o0.y = acc[nt][1]*inv0;
        o1.x = acc[nt][2]*inv1; o1.y = acc[nt][3]*inv1;
        *(float2*)&out[((size_t)b*SS + srow    )*HH + h*DHH + d] = o0;
        *(float2*)&out[((size_t)b*SS + srow + 8)*HH + h*DHH + d] = o1;
    }
}

extern "C" void kernel_launch(void* const* d_in, const int* in_sizes, int n_in,
                              void* d_out, int out_size)
{
    const float* hid  = (const float*)d_in[0];
    const float* bias = (const float*)d_in[1];
    const float* Wq   = (const float*)d_in[2];
    const float* bq   = (const float*)d_in[3];
    const float* Wk   = (const float*)d_in[4];
    const float* bk   = (const float*)d_in[5];
    const float* Wv   = (const float*)d_in[6];
    const float* bv   = (const float*)d_in[7];
    float* out = (float*)d_out;
    (void)in_sizes; (void)n_in; (void)out_size;

    cudaFuncSetAttribute(attn_kernel, cudaFuncAttributeMaxDynamicSharedMemorySize,
                         ATTN_SMEM_U32 * (int)sizeof(unsigned));

    dim3 g1(HH/64, (BB*SS)/128, 3);
    qkv_kernel<<<g1, 256>>>(hid, Wq, bq, Wk, bk, Wv, bv);

    dim3 g2(SS/128, NHH, BB);
    attn_kernel<<<g2, 256, ATTN_SMEM_U32 * (int)sizeof(unsigned)>>>(bias, out);
}

// round 3
// speedup vs baseline: 2.6937x; 1.0552x over previous
#include <cuda_runtime.h>
#include <cstdint>

#define BB   2
#define SS   2048
#define HH   1024
#define NHH  16
#define DHH  64

// Scratch: Q/K/V in [B, NH, S, DH] layout, values pre-rounded to tf32.
__device__ float g_q[BB*NHH*SS*DHH];
__device__ float g_k[BB*NHH*SS*DHH];
__device__ float g_v[BB*NHH*SS*DHH];

__device__ __forceinline__ unsigned f2tf32(float x) {
    unsigned t;
    asm("cvt.rna.tf32.f32 %0, %1;" : "=r"(t) : "f"(x));
    return t;
}

__device__ __forceinline__ void mma_tf32(float* c,
    unsigned a0, unsigned a1, unsigned a2, unsigned a3,
    unsigned b0, unsigned b1)
{
    asm volatile(
        "mma.sync.aligned.m16n8k8.row.col.f32.tf32.tf32.f32 "
        "{%0,%1,%2,%3}, {%4,%5,%6,%7}, {%8,%9}, {%0,%1,%2,%3};"
        : "+f"(c[0]), "+f"(c[1]), "+f"(c[2]), "+f"(c[3])
        : "r"(a0), "r"(a1), "r"(a2), "r"(a3), "r"(b0), "r"(b1));
}

__device__ __forceinline__ uint32_t smem_u32(const void* p) {
    return (uint32_t)__cvta_generic_to_shared(p);
}
__device__ __forceinline__ void cpa16(uint32_t s, const void* g) {
    asm volatile("cp.async.ca.shared.global [%0], [%1], 16;" :: "r"(s), "l"(g));
}
#define CP_COMMIT() asm volatile("cp.async.commit_group;")
#define CP_WAIT0()  asm volatile("cp.async.wait_group 0;")
#define CP_WAIT1()  asm volatile("cp.async.wait_group 1;")

// Fast exp on the FMA pipe. Rel err ~2.4e-6.
__device__ __forceinline__ float fexp(float x) {
    x = fmaxf(x, -87.0f);
    float y = x * 1.4426950408889634f;
    float r = y + 12582912.0f;
    float n = r - 12582912.0f;
    float f = y - n;
    float p = 1.3333558146e-3f;
    p = fmaf(p, f, 9.6181291076e-3f);
    p = fmaf(p, f, 5.5504108664e-2f);
    p = fmaf(p, f, 2.4022650696e-1f);
    p = fmaf(p, f, 6.9314718056e-1f);
    p = fmaf(p, f, 1.0f);
    int sc = (__float_as_int(r) - 0x4B400000 + 127) << 23;
    return p * __int_as_float(sc);
}

// ---------------------------------------------------------------------------
// QKV projection: 128x64 tile, ktile 32, register-prefetch double buffer.
// Outputs stored tf32-rounded in [B,NH,S,DH]; Q pre-scaled by 1/8.
// ---------------------------------------------------------------------------
__global__ __launch_bounds__(256, 2) void qkv_kernel(
    const float* __restrict__ hid,
    const float* __restrict__ Wq, const float* __restrict__ bq,
    const float* __restrict__ Wk, const float* __restrict__ bk,
    const float* __restrict__ Wv, const float* __restrict__ bv)
{
    const float* Wsrc; const float* bsrc; float* outp;
    if (blockIdx.z == 0)      { Wsrc = Wq; bsrc = bq; outp = g_q; }
    else if (blockIdx.z == 1) { Wsrc = Wk; bsrc = bk; outp = g_k; }
    else                      { Wsrc = Wv; bsrc = bv; outp = g_v; }

    __shared__ unsigned As[128*36];
    __shared__ unsigned Ws[64*36];

    const int tid  = threadIdx.x;
    const int warp = tid >> 5;
    const int lane = tid & 31;
    const int gid  = lane >> 2;
    const int tg   = lane & 3;
    const int m0   = blockIdx.y * 128;
    const int n0   = blockIdx.x * 64;
    const int mw   = warp * 16;

    const int lrow = tid >> 3;          // 0..31 (step 32 per it)
    const int lcol = (tid & 7) * 4;

    const float* Ap = hid  + (size_t)(m0 + lrow) * HH + lcol;
    const float* Wp = Wsrc + (size_t)(n0 + lrow) * HH + lcol;

    float4 ra[4], rw[2];
    #pragma unroll
    for (int it = 0; it < 4; it++) ra[it] = *(const float4*)(Ap + (size_t)it*32*HH);
    #pragma unroll
    for (int it = 0; it < 2; it++) rw[it] = *(const float4*)(Wp + (size_t)it*32*HH);

    float acc[8][4];
    #pragma unroll
    for (int i = 0; i < 8; i++)
        #pragma unroll
        for (int j = 0; j < 4; j++) acc[i][j] = 0.0f;

    for (int k0 = 0; k0 < HH; k0 += 32) {
        __syncthreads();
        #pragma unroll
        for (int it = 0; it < 4; it++) {
            uint4 u = make_uint4(f2tf32(ra[it].x), f2tf32(ra[it].y),
                                 f2tf32(ra[it].z), f2tf32(ra[it].w));
            *(uint4*)&As[(lrow + it*32)*36 + lcol] = u;
        }
        #pragma unroll
        for (int it = 0; it < 2; it++) {
            uint4 u = make_uint4(f2tf32(rw[it].x), f2tf32(rw[it].y),
                                 f2tf32(rw[it].z), f2tf32(rw[it].w));
            *(uint4*)&Ws[(lrow + it*32)*36 + lcol] = u;
        }
        __syncthreads();

        if (k0 + 32 < HH) {
            #pragma unroll
            for (int it = 0; it < 4; it++)
                ra[it] = *(const float4*)(Ap + k0 + 32 + (size_t)it*32*HH);
            #pragma unroll
            for (int it = 0; it < 2; it++)
                rw[it] = *(const float4*)(Wp + k0 + 32 + (size_t)it*32*HH);
        }

        #pragma unroll
        for (int ks = 0; ks < 4; ks++) {
            int kb = ks * 8;
            unsigned a0 = As[(mw+gid  )*36 + kb + tg];
            unsigned a1 = As[(mw+gid+8)*36 + kb + tg];
            unsigned a2 = As[(mw+gid  )*36 + kb + tg + 4];
            unsigned a3 = As[(mw+gid+8)*36 + kb + tg + 4];
            #pragma unroll
            for (int nt = 0; nt < 8; nt++) {
                unsigned b0 = Ws[(nt*8+gid)*36 + kb + tg];
                unsigned b1 = Ws[(nt*8+gid)*36 + kb + tg + 4];
                mma_tf32(acc[nt], a0, a1, a2, a3, b0, b1);
            }
        }
    }

    const int head = blockIdx.x;
    const float qscale = (blockIdx.z == 0) ? 0.125f : 1.0f;
    int m    = m0 + mw + gid;
    int bat0 = m >> 11,     srow0 = m & (SS-1);
    int bat1 = (m+8) >> 11, srow1 = (m+8) & (SS-1);
    #pragma unroll
    for (int nt = 0; nt < 8; nt++) {
        int d = nt*8 + tg*2;
        float b0 = bsrc[n0 + d], b1 = bsrc[n0 + d + 1];
        float2 o0, o1;
        o0.x = __uint_as_float(f2tf32((acc[nt][0]+b0)*qscale));
        o0.y = __uint_as_float(f2tf32((acc[nt][1]+b1)*qscale));
        o1.x = __uint_as_float(f2tf32((acc[nt][2]+b0)*qscale));
        o1.y = __uint_as_float(f2tf32((acc[nt][3]+b1)*qscale));
        *(float2*)&outp[(((size_t)bat0*NHH+head)*SS+srow0)*DHH + d] = o0;
        *(float2*)&outp[(((size_t)bat1*NHH+head)*SS+srow1)*DHH + d] = o1;
    }
}

// ---------------------------------------------------------------------------
// Attention: CTA = (b,h,128 q-rows), kv tile 64, cp.async double-buffered K/V,
// bias staged through the P smem region (layout-identical), no max pass.
// ---------------------------------------------------------------------------
#define KSTR 68
#define VSTR 72
#define SM_PQ (128*KSTR)
#define SM_K  (64*KSTR)
#define SM_V  (64*VSTR)
#define ATTN_SMEM_U32 (SM_PQ + 2*SM_K + 2*SM_V)

__global__ __launch_bounds__(256, 2) void attn_kernel(
    const float* __restrict__ bias, float* __restrict__ out)
{
    extern __shared__ unsigned sm[];
    unsigned* PQs = sm;
    unsigned* Ks  = PQs + SM_PQ;     // 2 stages
    unsigned* Vs  = Ks + 2*SM_K;     // 2 stages

    const int tid  = threadIdx.x;
    const int warp = tid >> 5;
    const int lane = tid & 31;
    const int gid  = lane >> 2;
    const int tg   = lane & 3;
    const int q0   = blockIdx.x * 128;
    const int h    = blockIdx.y;
    const int b    = blockIdx.z;
    const int mw   = warp * 16;

    const float* Qg = g_q + (((size_t)b*NHH + h)*SS + q0)*DHH;
    const float* Kg = g_k + (((size_t)b*NHH + h)*SS)*DHH;
    const float* Vg = g_v + (((size_t)b*NHH + h)*SS)*DHH;
    const float* Bg = bias + ((size_t)h*SS + q0)*SS;

    const uint32_t pq_b = smem_u32(PQs);
    const uint32_t k_b  = smem_u32(Ks);
    const uint32_t v_b  = smem_u32(Vs);

    const int crow = tid >> 4;            // 0..15 (+16 per it)
    const int ccol = (tid & 15) * 4;

    // Q tile -> PQ (group 1)
    #pragma unroll
    for (int it = 0; it < 8; it++) {
        int row = crow + it*16;
        cpa16(pq_b + (uint32_t)(row*KSTR + ccol)*4, Qg + (size_t)row*DHH + ccol);
    }
    CP_COMMIT();
    // K/V stage 0 (group 2)
    #pragma unroll
    for (int it = 0; it < 4; it++) {
        int row = crow + it*16;
        cpa16(k_b + (uint32_t)(row*KSTR + ccol)*4, Kg + (size_t)row*DHH + ccol);
        cpa16(v_b + (uint32_t)(row*VSTR + ccol)*4, Vg + (size_t)row*DHH + ccol);
    }
    CP_COMMIT();

    CP_WAIT1();            // Q landed
    __syncthreads();

    unsigned qa[8][4];
    #pragma unroll
    for (int ks = 0; ks < 8; ks++) {
        int kb = ks*8;
        qa[ks][0] = PQs[(mw+gid  )*KSTR + kb + tg];
        qa[ks][1] = PQs[(mw+gid+8)*KSTR + kb + tg];
        qa[ks][2] = PQs[(mw+gid  )*KSTR + kb + tg + 4];
        qa[ks][3] = PQs[(mw+gid+8)*KSTR + kb + tg + 4];
    }

    float acc[8][4];
    #pragma unroll
    for (int i = 0; i < 8; i++)
        #pragma unroll
        for (int j = 0; j < 4; j++) acc[i][j] = 0.0f;
    float lsum0 = 0.0f, lsum1 = 0.0f;

    const int r0 = mw + gid, r1 = r0 + 8;
    float* PQf = (float*)PQs;

    for (int kt = 0; kt < SS/64; kt++) {
        const int kv0 = kt * 64;
        const int cur = kt & 1;

        CP_WAIT0();              // K/V(kt) landed
        __syncthreads();         // ...and visible; PQ free (PV of kt-1 done)

        // bias(kt) -> PQ region (async, consumed after QK chain)
        #pragma unroll
        for (int it = 0; it < 8; it++) {
            int row = crow + it*16;
            cpa16(pq_b + (uint32_t)(row*KSTR + ccol)*4,
                  Bg + (size_t)row*SS + kv0 + ccol);
        }
        CP_COMMIT();

        const unsigned* Kc = Ks + cur*SM_K;
        const unsigned* Vc = Vs + cur*SM_V;

        #pragma unroll
        for (int half = 0; half < 2; half++) {
            float s[4][4];
            #pragma unroll
            for (int i = 0; i < 4; i++)
                #pragma unroll
                for (int j = 0; j < 4; j++) s[i][j] = 0.0f;
            #pragma unroll
            for (int ks = 0; ks < 8; ks++) {
                int kb = ks*8;
                #pragma unroll
                for (int n4 = 0; n4 < 4; n4++) {
                    int nt = half*4 + n4;
                    unsigned b0 = Kc[(nt*8+gid)*KSTR + kb + tg];
                    unsigned b1 = Kc[(nt*8+gid)*KSTR + kb + tg + 4];
                    mma_tf32(s[n4], qa[ks][0], qa[ks][1], qa[ks][2], qa[ks][3], b0, b1);
                }
            }
            if (half == 0) {
                CP_WAIT0();          // bias landed
                __syncthreads();     // visible to all
            }
            #pragma unroll
            for (int n4 = 0; n4 < 4; n4++) {
                int nt = half*4 + n4;
                int c  = nt*8 + tg*2;
                float2 bv0 = *(const float2*)&PQf[r0*KSTR + c];
                float2 bv1 = *(const float2*)&PQf[r1*KSTR + c];
                float p0 = __uint_as_float(f2tf32(fexp(s[n4][0] + bv0.x)));
                float p1 = __uint_as_float(f2tf32(fexp(s[n4][1] + bv0.y)));
                float p2 = __uint_as_float(f2tf32(fexp(s[n4][2] + bv1.x)));
                float p3 = __uint_as_float(f2tf32(fexp(s[n4][3] + bv1.y)));
                lsum0 += p0 + p1;
                lsum1 += p2 + p3;
                float2 w0 = make_float2(p0, p1);
                float2 w1 = make_float2(p2, p3);
                *(float2*)&PQf[r0*KSTR + c] = w0;   // own slots: no hazard
                *(float2*)&PQf[r1*KSTR + c] = w1;
            }
        }
        __syncthreads();    // P visible

        // prefetch K/V(kt+1)
        if (kt + 1 < SS/64) {
            const int nxt = cur ^ 1;
            #pragma unroll
            for (int it = 0; it < 4; it++) {
                int row = crow + it*16;
                cpa16(k_b + (uint32_t)(nxt*SM_K + row*KSTR + ccol)*4,
                      Kg + (size_t)(kv0 + 64 + row)*DHH + ccol);
                cpa16(v_b + (uint32_t)(nxt*SM_V + row*VSTR + ccol)*4,
                      Vg + (size_t)(kv0 + 64 + row)*DHH + ccol);
            }
            CP_COMMIT();
        }

        // acc += P V
        #pragma unroll
        for (int ks = 0; ks < 8; ks++) {
            int kb = ks*8;
            unsigned a0 = PQs[(mw+gid  )*KSTR + kb + tg];
            unsigned a1 = PQs[(mw+gid+8)*KSTR + kb + tg];
            unsigned a2 = PQs[(mw+gid  )*KSTR + kb + tg + 4];
            unsigned a3 = PQs[(mw+gid+8)*KSTR + kb + tg + 4];
            #pragma unroll
            for (int nt = 0; nt < 8; nt++) {
                unsigned b0 = Vc[(kb+tg  )*VSTR + nt*8 + gid];
                unsigned b1 = Vc[(kb+tg+4)*VSTR + nt*8 + gid];
                mma_tf32(acc[nt], a0, a1, a2, a3, b0, b1);
            }
        }
    }

    lsum0 += __shfl_xor_sync(0xFFFFFFFFu, lsum0, 1);
    lsum0 += __shfl_xor_sync(0xFFFFFFFFu, lsum0, 2);
    lsum1 += __shfl_xor_sync(0xFFFFFFFFu, lsum1, 1);
    lsum1 += __shfl_xor_sync(0xFFFFFFFFu, lsum1, 2);
    float inv0 = 1.0f / lsum0;
    float inv1 = 1.0f / lsum1;

    int srow = q0 + mw + gid;
    #pragma unroll
    for (int nt = 0; nt < 8; nt++) {
        int d = nt*8 + tg*2;
        float2 o0, o1;
        o0.x = acc[nt][0]*inv0; o0.y = acc[nt][1]*inv0;
        o1.x = acc[nt][2]*inv1; o1.y = acc[nt][3]*inv1;
        *(float2*)&out[((size_t)b*SS + srow    )*HH + h*DHH + d] = o0;
        *(float2*)&out[((size_t)b*SS + srow + 8)*HH + h*DHH + d] = o1;
    }
}

extern "C" void kernel_launch(void* const* d_in, const int* in_sizes, int n_in,
                              void* d_out, int out_size)
{
    const float* hid  = (const float*)d_in[0];
    const float* bias = (const float*)d_in[1];
    const float* Wq   = (const float*)d_in[2];
    const float* bq   = (const float*)d_in[3];
    const float* Wk   = (const float*)d_in[4];
    const float* bk   = (const float*)d_in[5];
    const float* Wv   = (const float*)d_in[6];
    const float* bv   = (const float*)d_in[7];
    float* out = (float*)d_out;
    (void)in_sizes; (void)n_in; (void)out_size;

    cudaFuncSetAttribute(attn_kernel, cudaFuncAttributeMaxDynamicSharedMemorySize,
                         ATTN_SMEM_U32 * (int)sizeof(unsigned));

    dim3 g1(HH/64, (BB*SS)/128, 3);
    qkv_kernel<<<g1, 256>>>(hid, Wq, bq, Wk, bk, Wv, bv);

    dim3 g2(SS/128, NHH, BB);
    attn_kernel<<<g2, 256, ATTN_SMEM_U32 * (int)sizeof(unsigned)>>>(bias, out);
}

// round 4
// speedup vs baseline: 2.8217x; 1.0475x over previous
#include <cuda_runtime.h>
#include <cstdint>

#define BB   2
#define SS   2048
#define HH   1024
#define NHH  16
#define DHH  64

// Scratch: Q/K/V in [B, NH, S, DH] layout, values pre-rounded to tf32.
__device__ float g_q[BB*NHH*SS*DHH];
__device__ float g_k[BB*NHH*SS*DHH];
__device__ float g_v[BB*NHH*SS*DHH];

__device__ __forceinline__ unsigned f2tf32(float x) {
    unsigned t;
    asm("cvt.rna.tf32.f32 %0, %1;" : "=r"(t) : "f"(x));
    return t;
}

__device__ __forceinline__ void mma_tf32(float* c,
    unsigned a0, unsigned a1, unsigned a2, unsigned a3,
    unsigned b0, unsigned b1)
{
    asm volatile(
        "mma.sync.aligned.m16n8k8.row.col.f32.tf32.tf32.f32 "
        "{%0,%1,%2,%3}, {%4,%5,%6,%7}, {%8,%9}, {%0,%1,%2,%3};"
        : "+f"(c[0]), "+f"(c[1]), "+f"(c[2]), "+f"(c[3])
        : "r"(a0), "r"(a1), "r"(a2), "r"(a3), "r"(b0), "r"(b1));
}

__device__ __forceinline__ uint32_t smem_u32(const void* p) {
    return (uint32_t)__cvta_generic_to_shared(p);
}
__device__ __forceinline__ void cpa16(uint32_t s, const void* g) {
    asm volatile("cp.async.ca.shared.global [%0], [%1], 16;" :: "r"(s), "l"(g));
}
#define CP_COMMIT() asm volatile("cp.async.commit_group;")
#define CP_WAIT0()  asm volatile("cp.async.wait_group 0;")
#define CP_WAIT1()  asm volatile("cp.async.wait_group 1;")

// Fast exp on the FMA pipe. Rel err ~2.4e-6.
__device__ __forceinline__ float fexp(float x) {
    x = fmaxf(x, -87.0f);
    float y = x * 1.4426950408889634f;
    float r = y + 12582912.0f;
    float n = r - 12582912.0f;
    float f = y - n;
    float p = 1.3333558146e-3f;
    p = fmaf(p, f, 9.6181291076e-3f);
    p = fmaf(p, f, 5.5504108664e-2f);
    p = fmaf(p, f, 2.4022650696e-1f);
    p = fmaf(p, f, 6.9314718056e-1f);
    p = fmaf(p, f, 1.0f);
    int sc = (__float_as_int(r) - 0x4B400000 + 127) << 23;
    return p * __int_as_float(sc);
}

// ---------------------------------------------------------------------------
// QKV projection: 128x64 tile, ktile 32, smem double-buffered, ONE sync/iter.
// Outputs stored tf32-rounded in [B,NH,S,DH]; Q pre-scaled by 1/8.
// ---------------------------------------------------------------------------
#define QA_STG (128*36)
#define QW_STG (64*36)
#define QKV_SMEM_U32 (2*QA_STG + 2*QW_STG)

__global__ __launch_bounds__(256, 2) void qkv_kernel(
    const float* __restrict__ hid,
    const float* __restrict__ Wq, const float* __restrict__ bq,
    const float* __restrict__ Wk, const float* __restrict__ bk,
    const float* __restrict__ Wv, const float* __restrict__ bv)
{
    const float* Wsrc; const float* bsrc; float* outp;
    if (blockIdx.z == 0)      { Wsrc = Wq; bsrc = bq; outp = g_q; }
    else if (blockIdx.z == 1) { Wsrc = Wk; bsrc = bk; outp = g_k; }
    else                      { Wsrc = Wv; bsrc = bv; outp = g_v; }

    extern __shared__ unsigned smq[];
    unsigned* As = smq;                 // 2 stages
    unsigned* Ws = smq + 2*QA_STG;      // 2 stages

    const int tid  = threadIdx.x;
    const int warp = tid >> 5;
    const int lane = tid & 31;
    const int gid  = lane >> 2;
    const int tg   = lane & 3;
    const int m0   = blockIdx.y * 128;
    const int n0   = blockIdx.x * 64;
    const int mw   = warp * 16;

    const int lrow = tid >> 3;          // 0..31 (step 32 per it)
    const int lcol = (tid & 7) * 4;

    const float* Ap = hid  + (size_t)(m0 + lrow) * HH + lcol;
    const float* Wp = Wsrc + (size_t)(n0 + lrow) * HH + lcol;

    float4 ra[4], rw[2];

    // prologue: tile 0 -> stage 0, then preload tile 1 regs
    #pragma unroll
    for (int it = 0; it < 4; it++) ra[it] = *(const float4*)(Ap + (size_t)it*32*HH);
    #pragma unroll
    for (int it = 0; it < 2; it++) rw[it] = *(const float4*)(Wp + (size_t)it*32*HH);
    #pragma unroll
    for (int it = 0; it < 4; it++) {
        uint4 u = make_uint4(f2tf32(ra[it].x), f2tf32(ra[it].y),
                             f2tf32(ra[it].z), f2tf32(ra[it].w));
        *(uint4*)&As[(lrow + it*32)*36 + lcol] = u;
    }
    #pragma unroll
    for (int it = 0; it < 2; it++) {
        uint4 u = make_uint4(f2tf32(rw[it].x), f2tf32(rw[it].y),
                             f2tf32(rw[it].z), f2tf32(rw[it].w));
        *(uint4*)&Ws[(lrow + it*32)*36 + lcol] = u;
    }
    #pragma unroll
    for (int it = 0; it < 4; it++) ra[it] = *(const float4*)(Ap + 32 + (size_t)it*32*HH);
    #pragma unroll
    for (int it = 0; it < 2; it++) rw[it] = *(const float4*)(Wp + 32 + (size_t)it*32*HH);
    __syncthreads();

    float acc[8][4];
    #pragma unroll
    for (int i = 0; i < 8; i++)
        #pragma unroll
        for (int j = 0; j < 4; j++) acc[i][j] = 0.0f;

    for (int kt = 0; kt < 32; kt++) {
        const int cur = kt & 1;
        const unsigned* Ac = As + cur*QA_STG;
        const unsigned* Wc = Ws + cur*QW_STG;

        // store (kt+1) regs -> nxt stage, issue LDG for kt+2
        if (kt + 1 < 32) {
            unsigned* An = As + (cur^1)*QA_STG;
            unsigned* Wn = Ws + (cur^1)*QW_STG;
            #pragma unroll
            for (int it = 0; it < 4; it++) {
                uint4 u = make_uint4(f2tf32(ra[it].x), f2tf32(ra[it].y),
                                     f2tf32(ra[it].z), f2tf32(ra[it].w));
                *(uint4*)&An[(lrow + it*32)*36 + lcol] = u;
            }
            #pragma unroll
            for (int it = 0; it < 2; it++) {
                uint4 u = make_uint4(f2tf32(rw[it].x), f2tf32(rw[it].y),
                                     f2tf32(rw[it].z), f2tf32(rw[it].w));
                *(uint4*)&Wn[(lrow + it*32)*36 + lcol] = u;
            }
        }
        if (kt + 2 < 32) {
            int k0 = (kt + 2) * 32;
            #pragma unroll
            for (int it = 0; it < 4; it++)
                ra[it] = *(const float4*)(Ap + k0 + (size_t)it*32*HH);
            #pragma unroll
            for (int it = 0; it < 2; it++)
                rw[it] = *(const float4*)(Wp + k0 + (size_t)it*32*HH);
        }

        #pragma unroll
        for (int ks = 0; ks < 4; ks++) {
            int kb = ks * 8;
            unsigned a0 = Ac[(mw+gid  )*36 + kb + tg];
            unsigned a1 = Ac[(mw+gid+8)*36 + kb + tg];
            unsigned a2 = Ac[(mw+gid  )*36 + kb + tg + 4];
            unsigned a3 = Ac[(mw+gid+8)*36 + kb + tg + 4];
            #pragma unroll
            for (int nt = 0; nt < 8; nt++) {
                unsigned b0 = Wc[(nt*8+gid)*36 + kb + tg];
                unsigned b1 = Wc[(nt*8+gid)*36 + kb + tg + 4];
                mma_tf32(acc[nt], a0, a1, a2, a3, b0, b1);
            }
        }
        __syncthreads();
    }

    const int head = blockIdx.x;
    const float qscale = (blockIdx.z == 0) ? 0.125f : 1.0f;
    int m    = m0 + mw + gid;
    int bat0 = m >> 11,     srow0 = m & (SS-1);
    int bat1 = (m+8) >> 11, srow1 = (m+8) & (SS-1);
    #pragma unroll
    for (int nt = 0; nt < 8; nt++) {
        int d = nt*8 + tg*2;
        float b0 = bsrc[n0 + d], b1 = bsrc[n0 + d + 1];
        float2 o0, o1;
        o0.x = __uint_as_float(f2tf32((acc[nt][0]+b0)*qscale));
        o0.y = __uint_as_float(f2tf32((acc[nt][1]+b1)*qscale));
        o1.x = __uint_as_float(f2tf32((acc[nt][2]+b0)*qscale));
        o1.y = __uint_as_float(f2tf32((acc[nt][3]+b1)*qscale));
        *(float2*)&outp[(((size_t)bat0*NHH+head)*SS+srow0)*DHH + d] = o0;
        *(float2*)&outp[(((size_t)bat1*NHH+head)*SS+srow1)*DHH + d] = o1;
    }
}

// ---------------------------------------------------------------------------
// Attention: CTA = (b,h,128 q-rows). P tile is WARP-PRIVATE (rows 16w..16w+16),
// bias loaded straight to registers -> no CTA barrier around exp.
// Only 2 barriers/iter, both for the K/V cp.async stage swap.
// ---------------------------------------------------------------------------
#define KSTR 68
#define VSTR 72
#define SM_PQ (128*KSTR)
#define SM_K  (64*KSTR)
#define SM_V  (64*VSTR)
#define ATTN_SMEM_U32 (SM_PQ + 2*SM_K + 2*SM_V)
#define NT (SS/64)

__global__ __launch_bounds__(256, 2) void attn_kernel(
    const float* __restrict__ bias, float* __restrict__ out)
{
    extern __shared__ unsigned sm[];
    unsigned* PQs = sm;              // Q tile at start, then per-warp P tiles
    unsigned* Ks  = PQs + SM_PQ;     // 2 stages
    unsigned* Vs  = Ks + 2*SM_K;     // 2 stages

    const int tid  = threadIdx.x;
    const int warp = tid >> 5;
    const int lane = tid & 31;
    const int gid  = lane >> 2;
    const int tg   = lane & 3;
    const int q0   = blockIdx.x * 128;
    const int h    = blockIdx.y;
    const int b    = blockIdx.z;
    const int mw   = warp * 16;

    const float* Qg = g_q + (((size_t)b*NHH + h)*SS + q0)*DHH;
    const float* Kg = g_k + (((size_t)b*NHH + h)*SS)*DHH;
    const float* Vg = g_v + (((size_t)b*NHH + h)*SS)*DHH;
    const float* Bg = bias + ((size_t)h*SS + q0)*SS;

    const uint32_t pq_b = smem_u32(PQs);
    const uint32_t k_b  = smem_u32(Ks);
    const uint32_t v_b  = smem_u32(Vs);

    const int crow = tid >> 4;            // 0..15 (+16 per it)
    const int ccol = (tid & 15) * 4;

    // Q tile -> PQ (group 1)
    #pragma unroll
    for (int it = 0; it < 8; it++) {
        int row = crow + it*16;
        cpa16(pq_b + (uint32_t)(row*KSTR + ccol)*4, Qg + (size_t)row*DHH + ccol);
    }
    CP_COMMIT();
    // K/V stage 0 (group 2)
    #pragma unroll
    for (int it = 0; it < 4; it++) {
        int row = crow + it*16;
        cpa16(k_b + (uint32_t)(row*KSTR + ccol)*4, Kg + (size_t)row*DHH + ccol);
        cpa16(v_b + (uint32_t)(row*VSTR + ccol)*4, Vg + (size_t)row*DHH + ccol);
    }
    CP_COMMIT();

    CP_WAIT1();            // Q landed
    __syncthreads();

    unsigned qa[8][4];
    #pragma unroll
    for (int ks = 0; ks < 8; ks++) {
        int kb = ks*8;
        qa[ks][0] = PQs[(mw+gid  )*KSTR + kb + tg];
        qa[ks][1] = PQs[(mw+gid+8)*KSTR + kb + tg];
        qa[ks][2] = PQs[(mw+gid  )*KSTR + kb + tg + 4];
        qa[ks][3] = PQs[(mw+gid+8)*KSTR + kb + tg + 4];
    }

    float acc[8][4];
    #pragma unroll
    for (int i = 0; i < 8; i++)
        #pragma unroll
        for (int j = 0; j < 4; j++) acc[i][j] = 0.0f;
    float lsum0 = 0.0f, lsum1 = 0.0f;

    const int r0 = mw + gid, r1 = r0 + 8;
    float* PQf = (float*)PQs;
    const float* Brow0 = Bg + (size_t)r0*SS;
    const float* Brow1 = Bg + (size_t)r1*SS;

    for (int kt = 0; kt < NT; kt++) {
        const int cur = kt & 1;
        const int kv0 = kt * 64;

        __syncthreads();              // (a) all warps done reading stage nxt
        if (kt + 1 < NT) {
            const int nxt = cur ^ 1;
            #pragma unroll
            for (int it = 0; it < 4; it++) {
                int row = crow + it*16;
                cpa16(k_b + (uint32_t)(nxt*SM_K + row*KSTR + ccol)*4,
                      Kg + (size_t)(kv0 + 64 + row)*DHH + ccol);
                cpa16(v_b + (uint32_t)(nxt*SM_V + row*VSTR + ccol)*4,
                      Vg + (size_t)(kv0 + 64 + row)*DHH + ccol);
            }
            CP_COMMIT();
            CP_WAIT1();               // K/V(kt) landed; (kt+1) may fly
        } else {
            CP_WAIT0();
        }
        __syncthreads();              // (b) K/V(kt) visible to all warps

        const unsigned* Kc = Ks + cur*SM_K;
        const unsigned* Vc = Vs + cur*SM_V;

        // Two n-halves; everything here is warp-local (P rows are private)
        #pragma unroll
        for (int half = 0; half < 2; half++) {
            // bias straight to registers; QK chain below hides the latency
            float2 bv0[4], bv1[4];
            #pragma unroll
            for (int n4 = 0; n4 < 4; n4++) {
                int c = (half*4 + n4)*8 + tg*2;
                bv0[n4] = *(const float2*)(Brow0 + kv0 + c);
                bv1[n4] = *(const float2*)(Brow1 + kv0 + c);
            }
            float s[4][4];
            #pragma unroll
            for (int i = 0; i < 4; i++)
                #pragma unroll
                for (int j = 0; j < 4; j++) s[i][j] = 0.0f;
            #pragma unroll
            for (int ks = 0; ks < 8; ks++) {
                int kb = ks*8;
                #pragma unroll
                for (int n4 = 0; n4 < 4; n4++) {
                    int nt = half*4 + n4;
                    unsigned b0 = Kc[(nt*8+gid)*KSTR + kb + tg];
                    unsigned b1 = Kc[(nt*8+gid)*KSTR + kb + tg + 4];
                    mma_tf32(s[n4], qa[ks][0], qa[ks][1], qa[ks][2], qa[ks][3], b0, b1);
                }
            }
            #pragma unroll
            for (int n4 = 0; n4 < 4; n4++) {
                int c = (half*4 + n4)*8 + tg*2;
                float p0 = __uint_as_float(f2tf32(fexp(s[n4][0] + bv0[n4].x)));
                float p1 = __uint_as_float(f2tf32(fexp(s[n4][1] + bv0[n4].y)));
                float p2 = __uint_as_float(f2tf32(fexp(s[n4][2] + bv1[n4].x)));
                float p3 = __uint_as_float(f2tf32(fexp(s[n4][3] + bv1[n4].y)));
                lsum0 += p0 + p1;
                lsum1 += p2 + p3;
                *(float2*)&PQf[r0*KSTR + c] = make_float2(p0, p1);
                *(float2*)&PQf[r1*KSTR + c] = make_float2(p2, p3);
            }
        }
        __syncwarp();     // order P writes before fragment reads (same warp)

        // acc += P V   (A-fragments from this warp's own P rows)
        #pragma unroll
        for (int ks = 0; ks < 8; ks++) {
            int kb = ks*8;
            unsigned a0 = PQs[(mw+gid  )*KSTR + kb + tg];
            unsigned a1 = PQs[(mw+gid+8)*KSTR + kb + tg];
            unsigned a2 = PQs[(mw+gid  )*KSTR + kb + tg + 4];
            unsigned a3 = PQs[(mw+gid+8)*KSTR + kb + tg + 4];
            #pragma unroll
            for (int nt = 0; nt < 8; nt++) {
                unsigned b0 = Vc[(kb+tg  )*VSTR + nt*8 + gid];
                unsigned b1 = Vc[(kb+tg+4)*VSTR + nt*8 + gid];
                mma_tf32(acc[nt], a0, a1, a2, a3, b0, b1);
            }
        }
    }

    lsum0 += __shfl_xor_sync(0xFFFFFFFFu, lsum0, 1);
    lsum0 += __shfl_xor_sync(0xFFFFFFFFu, lsum0, 2);
    lsum1 += __shfl_xor_sync(0xFFFFFFFFu, lsum1, 1);
    lsum1 += __shfl_xor_sync(0xFFFFFFFFu, lsum1, 2);
    float inv0 = 1.0f / lsum0;
    float inv1 = 1.0f / lsum1;

    int srow = q0 + mw + gid;
    #pragma unroll
    for (int nt = 0; nt < 8; nt++) {
        int d = nt*8 + tg*2;
        float2 o0, o1;
        o0.x = acc[nt][0]*inv0; o0.y = acc[nt][1]*inv0;
        o1.x = acc[nt][2]*inv1; o1.y = acc[nt][3]*inv1;
        *(float2*)&out[((size_t)b*SS + srow    )*HH + h*DHH + d] = o0;
        *(float2*)&out[((size_t)b*SS + srow + 8)*HH + h*DHH + d] = o1;
    }
}

extern "C" void kernel_launch(void* const* d_in, const int* in_sizes, int n_in,
                              void* d_out, int out_size)
{
    const float* hid  = (const float*)d_in[0];
    const float* bias = (const float*)d_in[1];
    const float* Wq   = (const float*)d_in[2];
    const float* bq   = (const float*)d_in[3];
    const float* Wk   = (const float*)d_in[4];
    const float* bk   = (const float*)d_in[5];
    const float* Wv   = (const float*)d_in[6];
    const float* bv   = (const float*)d_in[7];
    float* out = (float*)d_out;
    (void)in_sizes; (void)n_in; (void)out_size;

    cudaFuncSetAttribute(qkv_kernel, cudaFuncAttributeMaxDynamicSharedMemorySize,
                         QKV_SMEM_U32 * (int)sizeof(unsigned));
    cudaFuncSetAttribute(attn_kernel, cudaFuncAttributeMaxDynamicSharedMemorySize,
                         ATTN_SMEM_U32 * (int)sizeof(unsigned));

    dim3 g1(HH/64, (BB*SS)/128, 3);
    qkv_kernel<<<g1, 256, QKV_SMEM_U32 * (int)sizeof(unsigned)>>>(
        hid, Wq, bq, Wk, bk, Wv, bv);

    dim3 g2(SS/128, NHH, BB);
    attn_kernel<<<g2, 256, ATTN_SMEM_U32 * (int)sizeof(unsigned)>>>(bias, out);
}

// round 6
// speedup vs baseline: 4.3785x; 1.5517x over previous
#include <cuda_runtime.h>
#include <cuda_fp16.h>
#include <cstdint>

#define BB   2
#define SS   2048
#define HH   1024
#define NHH  16
#define DHH  64
#define NT   (SS/64)

// Scratch: Q/K fp16 in [B,NH,S,DH]; V fp16 TRANSPOSED in [B,NH,DH,S].
__device__ __half g_q[BB*NHH*SS*DHH];
__device__ __half g_k[BB*NHH*SS*DHH];
__device__ __half g_v[BB*NHH*SS*DHH];

__device__ __forceinline__ void mma_f16(float* c,
    unsigned a0, unsigned a1, unsigned a2, unsigned a3,
    unsigned b0, unsigned b1)
{
    asm volatile(
        "mma.sync.aligned.m16n8k16.row.col.f32.f16.f16.f32 "
        "{%0,%1,%2,%3}, {%4,%5,%6,%7}, {%8,%9}, {%0,%1,%2,%3};"
        : "+f"(c[0]), "+f"(c[1]), "+f"(c[2]), "+f"(c[3])
        : "r"(a0), "r"(a1), "r"(a2), "r"(a3), "r"(b0), "r"(b1));
}

__device__ __forceinline__ uint32_t smem_u32(const void* p) {
    return (uint32_t)__cvta_generic_to_shared(p);
}
__device__ __forceinline__ void cpa16(uint32_t s, const void* g) {
    asm volatile("cp.async.ca.shared.global [%0], [%1], 16;" :: "r"(s), "l"(g));
}
#define CP_COMMIT() asm volatile("cp.async.commit_group;")
#define CP_WAIT0()  asm volatile("cp.async.wait_group 0;")
#define CP_WAIT1()  asm volatile("cp.async.wait_group 1;")

__device__ __forceinline__ unsigned packh2(float lo, float hi) {
    __half2 h = __floats2half2_rn(lo, hi);
    return *(unsigned*)&h;
}

// Fast exp on the FMA pipe. Rel err ~2.4e-6.
__device__ __forceinline__ float fexp(float x) {
    x = fmaxf(x, -87.0f);
    float y = x * 1.4426950408889634f;
    float r = y + 12582912.0f;
    float n = r - 12582912.0f;
    float f = y - n;
    float p = 1.3333558146e-3f;
    p = fmaf(p, f, 9.6181291076e-3f);
    p = fmaf(p, f, 5.5504108664e-2f);
    p = fmaf(p, f, 2.4022650696e-1f);
    p = fmaf(p, f, 6.9314718056e-1f);
    p = fmaf(p, f, 1.0f);
    int sc = (__float_as_int(r) - 0x4B400000 + 127) << 23;
    return p * __int_as_float(sc);
}

// ---------------------------------------------------------------------------
// QKV projection: 128x64 tile, ktile 32 (= 2 fp16 ksteps), smem double-buffer,
// one sync/iter. Outputs fp16; Q pre-scaled 1/8; V transposed [B,NH,DH,S].
// Smem element = half2 (unsigned). Row strides 20 (==4 mod 16 u32 banks ok).
// ---------------------------------------------------------------------------
#define QA_STG (128*20)
#define QW_STG (64*20)
#define QKV_SMEM_U32 (2*QA_STG + 2*QW_STG)

__global__ __launch_bounds__(256, 2) void qkv_kernel(
    const float* __restrict__ hid,
    const float* __restrict__ Wq, const float* __restrict__ bq,
    const float* __restrict__ Wk, const float* __restrict__ bk,
    const float* __restrict__ Wv, const float* __restrict__ bv)
{
    const float* Wsrc; const float* bsrc;
    if (blockIdx.z == 0)      { Wsrc = Wq; bsrc = bq; }
    else if (blockIdx.z == 1) { Wsrc = Wk; bsrc = bk; }
    else                      { Wsrc = Wv; bsrc = bv; }

    extern __shared__ unsigned smq[];
    unsigned* As = smq;                 // 2 stages, [128][20] half2
    unsigned* Ws = smq + 2*QA_STG;      // 2 stages, [64][20]

    const int tid  = threadIdx.x;
    const int warp = tid >> 5;
    const int lane = tid & 31;
    const int gid  = lane >> 2;
    const int tg   = lane & 3;
    const int m0   = blockIdx.y * 128;
    const int n0   = blockIdx.x * 64;
    const int mw   = warp * 16;

    const int lrow = tid >> 3;          // 0..31 (step 32 per it)
    const int lcol = tid & 7;           // fp32 col = lcol*4; half2 col = lcol*2

    const float* Ap = hid  + (size_t)(m0 + lrow) * HH + lcol*4;
    const float* Wp = Wsrc + (size_t)(n0 + lrow) * HH + lcol*4;

    float4 ra[4], rw[2];
    #pragma unroll
    for (int it = 0; it < 4; it++) ra[it] = *(const float4*)(Ap + (size_t)it*32*HH);
    #pragma unroll
    for (int it = 0; it < 2; it++) rw[it] = *(const float4*)(Wp + (size_t)it*32*HH);
    #pragma unroll
    for (int it = 0; it < 4; it++) {
        uint2 u = make_uint2(packh2(ra[it].x, ra[it].y), packh2(ra[it].z, ra[it].w));
        *(uint2*)&As[(lrow + it*32)*20 + lcol*2] = u;
    }
    #pragma unroll
    for (int it = 0; it < 2; it++) {
        uint2 u = make_uint2(packh2(rw[it].x, rw[it].y), packh2(rw[it].z, rw[it].w));
        *(uint2*)&Ws[(lrow + it*32)*20 + lcol*2] = u;
    }
    #pragma unroll
    for (int it = 0; it < 4; it++) ra[it] = *(const float4*)(Ap + 32 + (size_t)it*32*HH);
    #pragma unroll
    for (int it = 0; it < 2; it++) rw[it] = *(const float4*)(Wp + 32 + (size_t)it*32*HH);
    __syncthreads();

    float acc[8][4];
    #pragma unroll
    for (int i = 0; i < 8; i++)
        #pragma unroll
        for (int j = 0; j < 4; j++) acc[i][j] = 0.0f;

    for (int kt = 0; kt < 32; kt++) {
        const int cur = kt & 1;
        const unsigned* Ac = As + cur*QA_STG;
        const unsigned* Wc = Ws + cur*QW_STG;

        if (kt + 1 < 32) {
            unsigned* An = As + (cur^1)*QA_STG;
            unsigned* Wn = Ws + (cur^1)*QW_STG;
            #pragma unroll
            for (int it = 0; it < 4; it++) {
                uint2 u = make_uint2(packh2(ra[it].x, ra[it].y), packh2(ra[it].z, ra[it].w));
                *(uint2*)&An[(lrow + it*32)*20 + lcol*2] = u;
            }
            #pragma unroll
            for (int it = 0; it < 2; it++) {
                uint2 u = make_uint2(packh2(rw[it].x, rw[it].y), packh2(rw[it].z, rw[it].w));
                *(uint2*)&Wn[(lrow + it*32)*20 + lcol*2] = u;
            }
        }
        if (kt + 2 < 32) {
            int k0 = (kt + 2) * 32;
            #pragma unroll
            for (int it = 0; it < 4; it++)
                ra[it] = *(const float4*)(Ap + k0 + (size_t)it*32*HH);
            #pragma unroll
            for (int it = 0; it < 2; it++)
                rw[it] = *(const float4*)(Wp + k0 + (size_t)it*32*HH);
        }

        // 2 fp16 ksteps of k=16 each
        #pragma unroll
        for (int ks = 0; ks < 2; ks++) {
            int kb = ks * 8;                       // half2 col base
            unsigned a0 = Ac[(mw+gid  )*20 + kb + tg];
            unsigned a1 = Ac[(mw+gid+8)*20 + kb + tg];
            unsigned a2 = Ac[(mw+gid  )*20 + kb + tg + 4];
            unsigned a3 = Ac[(mw+gid+8)*20 + kb + tg + 4];
            #pragma unroll
            for (int nt = 0; nt < 8; nt++) {
                unsigned b0 = Wc[(nt*8+gid)*20 + kb + tg];
                unsigned b1 = Wc[(nt*8+gid)*20 + kb + tg + 4];
                mma_f16(acc[nt], a0, a1, a2, a3, b0, b1);
            }
        }
        __syncthreads();
    }

    const int head = blockIdx.x;
    int m    = m0 + mw + gid;
    int bat0 = m >> 11,     srow0 = m & (SS-1);
    int bat1 = (m+8) >> 11, srow1 = (m+8) & (SS-1);

    if (blockIdx.z == 2) {
        // V transposed: [B,NH,DH,S], scalar half stores
        size_t base0 = ((size_t)bat0*NHH + head)*DHH;
        size_t base1 = ((size_t)bat1*NHH + head)*DHH;
        #pragma unroll
        for (int nt = 0; nt < 8; nt++) {
            int d = nt*8 + tg*2;
            float b0 = bsrc[n0 + d], b1 = bsrc[n0 + d + 1];
            g_v[(base0 + d    )*SS + srow0] = __float2half_rn(acc[nt][0]+b0);
            g_v[(base0 + d + 1)*SS + srow0] = __float2half_rn(acc[nt][1]+b1);
            g_v[(base1 + d    )*SS + srow1] = __float2half_rn(acc[nt][2]+b0);
            g_v[(base1 + d + 1)*SS + srow1] = __float2half_rn(acc[nt][3]+b1);
        }
    } else {
        __half* outp = (blockIdx.z == 0) ? g_q : g_k;
        const float qscale = (blockIdx.z == 0) ? 0.125f : 1.0f;
        size_t rb0 = (((size_t)bat0*NHH+head)*SS+srow0)*DHH;
        size_t rb1 = (((size_t)bat1*NHH+head)*SS+srow1)*DHH;
        #pragma unroll
        for (int nt = 0; nt < 8; nt++) {
            int d = nt*8 + tg*2;
            float b0 = bsrc[n0 + d], b1 = bsrc[n0 + d + 1];
            *(unsigned*)&outp[rb0 + d] =
                packh2((acc[nt][0]+b0)*qscale, (acc[nt][1]+b1)*qscale);
            *(unsigned*)&outp[rb1 + d] =
                packh2((acc[nt][2]+b0)*qscale, (acc[nt][3]+b1)*qscale);
        }
    }
}

// ---------------------------------------------------------------------------
// Attention fp16: CTA = (b,h,128 q-rows), kv tile 64. P tile warp-private.
// All smem tiles stored as half2 (unsigned), row stride 36 half2.
// K smem: [kv][dh/2]; V smem: [dh][kv/2] (from transposed V); Q/P: [row][36].
// ---------------------------------------------------------------------------
#define STR 36
#define SM_PQ (128*STR)
#define SM_K  (64*STR)
#define SM_V  (64*STR)
#define ATTN_SMEM_U32 (SM_PQ + 2*SM_K + 2*SM_V)

__global__ __launch_bounds__(256, 2) void attn_kernel(
    const float* __restrict__ bias, float* __restrict__ out)
{
    extern __shared__ unsigned sm[];
    unsigned* PQs = sm;              // Q tile at start, then per-warp P tiles
    unsigned* Ks  = PQs + SM_PQ;     // 2 stages
    unsigned* Vs  = Ks + 2*SM_K;     // 2 stages

    const int tid  = threadIdx.x;
    const int warp = tid >> 5;
    const int lane = tid & 31;
    const int gid  = lane >> 2;
    const int tg   = lane & 3;
    const int q0   = blockIdx.x * 128;
    const int h    = blockIdx.y;
    const int b    = blockIdx.z;
    const int mw   = warp * 16;

    const __half* Qg  = g_q + (((size_t)b*NHH + h)*SS + q0)*DHH;
    const __half* Kg  = g_k + (((size_t)b*NHH + h)*SS)*DHH;
    const __half* Vtg = g_v + (((size_t)b*NHH + h)*DHH)*SS;    // [DH][S]
    const float*  Bg  = bias + ((size_t)h*SS + q0)*SS;

    const uint32_t pq_b = smem_u32(PQs);
    const uint32_t k_b  = smem_u32(Ks);
    const uint32_t v_b  = smem_u32(Vs);

    const int crow = tid >> 3;            // 0..31 (+32 per it)
    const int ccol = tid & 7;             // 16B chunk; half2 col = ccol*4

    // Q tile (128 rows x 8 chunks) -> PQ (group 1)
    #pragma unroll
    for (int it = 0; it < 4; it++) {
        int row = crow + it*32;
        cpa16(pq_b + (uint32_t)(row*STR + ccol*4)*4, Qg + (size_t)row*DHH + ccol*8);
    }
    CP_COMMIT();
    // K/V stage 0 (64 rows x 8 chunks each) (group 2)
    #pragma unroll
    for (int it = 0; it < 2; it++) {
        int row = crow + it*32;
        cpa16(k_b + (uint32_t)(row*STR + ccol*4)*4, Kg  + (size_t)row*DHH + ccol*8);
        cpa16(v_b + (uint32_t)(row*STR + ccol*4)*4, Vtg + (size_t)row*SS  + ccol*8);
    }
    CP_COMMIT();

    CP_WAIT1();            // Q landed
    __syncthreads();

    // Q fragments held in registers: 4 ksteps x 4 regs
    unsigned qa[4][4];
    #pragma unroll
    for (int ks = 0; ks < 4; ks++) {
        int kb = ks*8;
        qa[ks][0] = PQs[(mw+gid  )*STR + kb + tg];
        qa[ks][1] = PQs[(mw+gid+8)*STR + kb + tg];
        qa[ks][2] = PQs[(mw+gid  )*STR + kb + tg + 4];
        qa[ks][3] = PQs[(mw+gid+8)*STR + kb + tg + 4];
    }

    float acc[8][4];
    #pragma unroll
    for (int i = 0; i < 8; i++)
        #pragma unroll
        for (int j = 0; j < 4; j++) acc[i][j] = 0.0f;
    float lsum0 = 0.0f, lsum1 = 0.0f;

    const int r0 = mw + gid, r1 = r0 + 8;
    const float* Brow0 = Bg + (size_t)r0*SS;
    const float* Brow1 = Bg + (size_t)r1*SS;

    for (int kt = 0; kt < NT; kt++) {
        const int cur = kt & 1;
        const int kv0 = kt * 64;

        __syncthreads();              // all warps done reading stage nxt
        if (kt + 1 < NT) {
            const int nxt = cur ^ 1;
            #pragma unroll
            for (int it = 0; it < 2; it++) {
                int row = crow + it*32;
                cpa16(k_b + (uint32_t)(nxt*SM_K + row*STR + ccol*4)*4,
                      Kg + (size_t)(kv0 + 64 + row)*DHH + ccol*8);
                cpa16(v_b + (uint32_t)(nxt*SM_V + row*STR + ccol*4)*4,
                      Vtg + (size_t)row*SS + kv0 + 64 + ccol*8);
            }
            CP_COMMIT();
            CP_WAIT1();               // K/V(kt) landed; (kt+1) may fly
        } else {
            CP_WAIT0();
        }
        __syncthreads();              // K/V(kt) visible to all warps

        const unsigned* Kc = Ks + cur*SM_K;
        const unsigned* Vc = Vs + cur*SM_V;

        // Two n-halves; warp-local throughout (P rows are private)
        #pragma unroll
        for (int half = 0; half < 2; half++) {
            float2 bv0[4], bv1[4];
            #pragma unroll
            for (int n4 = 0; n4 < 4; n4++) {
                int c = (half*4 + n4)*8 + tg*2;
                bv0[n4] = *(const float2*)(Brow0 + kv0 + c);
                bv1[n4] = *(const float2*)(Brow1 + kv0 + c);
            }
            float s[4][4];
            #pragma unroll
            for (int i = 0; i < 4; i++)
                #pragma unroll
                for (int j = 0; j < 4; j++) s[i][j] = 0.0f;
            #pragma unroll
            for (int ks = 0; ks < 4; ks++) {
                int kb = ks*8;
                #pragma unroll
                for (int n4 = 0; n4 < 4; n4++) {
                    int nt = half*4 + n4;
                    unsigned b0 = Kc[(nt*8+gid)*STR + kb + tg];
                    unsigned b1 = Kc[(nt*8+gid)*STR + kb + tg + 4];
                    mma_f16(s[n4], qa[ks][0], qa[ks][1], qa[ks][2], qa[ks][3], b0, b1);
                }
            }
            #pragma unroll
            for (int n4 = 0; n4 < 4; n4++) {
                int nt = half*4 + n4;
                float p0 = fexp(s[n4][0] + bv0[n4].x);
                float p1 = fexp(s[n4][1] + bv0[n4].y);
                float p2 = fexp(s[n4][2] + bv1[n4].x);
                float p3 = fexp(s[n4][3] + bv1[n4].y);
                __half2 h0 = __floats2half2_rn(p0, p1);
                __half2 h1 = __floats2half2_rn(p2, p3);
                lsum0 += __half2float(h0.x) + __half2float(h0.y);
                lsum1 += __half2float(h1.x) + __half2float(h1.y);
                PQs[r0*STR + nt*4 + tg] = *(unsigned*)&h0;
                PQs[r1*STR + nt*4 + tg] = *(unsigned*)&h1;
            }
        }
        __syncwarp();     // order P writes before fragment reads (same warp)

        // acc += P V  (A from own P rows; B from V^T tile: rows=dh, cols=kv/2)
        #pragma unroll
        for (int ks = 0; ks < 4; ks++) {
            int kb = ks*8;
            unsigned a0 = PQs[r0*STR + kb + tg];
            unsigned a1 = PQs[r1*STR + kb + tg];
            unsigned a2 = PQs[r0*STR + kb + tg + 4];
            unsigned a3 = PQs[r1*STR + kb + tg + 4];
            #pragma unroll
            for (int nt = 0; nt < 8; nt++) {
                unsigned b0 = Vc[(nt*8+gid)*STR + kb + tg];
                unsigned b1 = Vc[(nt*8+gid)*STR + kb + tg + 4];
                mma_f16(acc[nt], a0, a1, a2, a3, b0, b1);
            }
        }
    }

    lsum0 += __shfl_xor_sync(0xFFFFFFFFu, lsum0, 1);
    lsum0 += __shfl_xor_sync(0xFFFFFFFFu, lsum0, 2);
    lsum1 += __shfl_xor_sync(0xFFFFFFFFu, lsum1, 1);
    lsum1 += __shfl_xor_sync(0xFFFFFFFFu, lsum1, 2);
    float inv0 = 1.0f / lsum0;
    float inv1 = 1.0f / lsum1;

    int srow = q0 + mw + gid;
    #pragma unroll
    for (int nt = 0; nt < 8; nt++) {
        int d = nt*8 + tg*2;
        float2 o0, o1;
        o0.x = acc[nt][0]*inv0; o0.y = acc[nt][1]*inv0;
        o1.x = acc[nt][2]*inv1; o1.y = acc[nt][3]*inv1;
        *(float2*)&out[((size_t)b*SS + srow    )*HH + h*DHH + d] = o0;
        *(float2*)&out[((size_t)b*SS + srow + 8)*HH + h*DHH + d] = o1;
    }
}

extern "C" void kernel_launch(void* const* d_in, const int* in_sizes, int n_in,
                              void* d_out, int out_size)
{
    const float* hid  = (const float*)d_in[0];
    const float* bias = (const float*)d_in[1];
    const float* Wq   = (const float*)d_in[2];
    const float* bq   = (const float*)d_in[3];
    const float* Wk   = (const float*)d_in[4];
    const float* bk   = (const float*)d_in[5];
    const float* Wv   = (const float*)d_in[6];
    const float* bv   = (const float*)d_in[7];
    float* out = (float*)d_out;
    (void)in_sizes; (void)n_in; (void)out_size;

    cudaFuncSetAttribute(qkv_kernel, cudaFuncAttributeMaxDynamicSharedMemorySize,
                         QKV_SMEM_U32 * (int)sizeof(unsigned));
    cudaFuncSetAttribute(attn_kernel, cudaFuncAttributeMaxDynamicSharedMemorySize,
                         ATTN_SMEM_U32 * (int)sizeof(unsigned));

    dim3 g1(HH/64, (BB*SS)/128, 3);
    qkv_kernel<<<g1, 256, QKV_SMEM_U32 * (int)sizeof(unsigned)>>>(
        hid, Wq, bq, Wk, bk, Wv, bv);

    dim3 g2(SS/128, NHH, BB);
    attn_kernel<<<g2, 256, ATTN_SMEM_U32 * (int)sizeof(unsigned)>>>(bias, out);
}